// round 15
// baseline (speedup 1.0000x reference)
#include <cuda_runtime.h>
#include <cstdint>

// ---------------------------------------------------------------------------
// Window-based self-attention (Swin-style), B=64, 56x56, C=128, WS=7, NH=8.
// Round 13: FULL fusion. One persistent-per-window kernel does
// LN + partition + QKV GEMM + attention + out-proj + window merge.
//   K0: transpose + tf32-round + k-permute weights -> g_wT
//   KF: everything else -> d_out
// smem stays 97.5KB -> 2 CTAs/SM (the R10 lesson).
// ---------------------------------------------------------------------------

#define SCALE_ATT 0.25f             // HD^-0.5, HD=16
#define LN_EPS    1e-5f
#define XS_LDA    132               // A / O row stride (floats)

__device__ float g_wT[384 * 128 + 128 * 128];        // wT_qkv | wT_out (tf32, k-permuted)

// fused smem layout (floats):
//   [0 .. 8448)          xs[64][132]  (A tile; aliased by vt slabs 8x960 in attn)
//   [8448 .. 24128)      8 x (q[49][20] | k[49][20]) ; aliased by os[64][132] in proj
//   tail pad 256 floats (q/k frag reads of rows 49..63 overrun slab end)
#define REG2_OFF   8448
#define FUSED_SMEM ((24128 + 256) * 4)   // 97536 B -> 2 CTAs/SM

// ---------------------------------------------------------------------------
// helpers
// ---------------------------------------------------------------------------
__device__ __forceinline__ float to_tf32(float x) {
    asm("cvt.rna.tf32.f32 %0, %0;" : "+f"(x));
    return x;
}
__device__ __forceinline__ void mma_tf32(float* c,
                                         uint32_t a0, uint32_t a1, uint32_t a2, uint32_t a3,
                                         uint32_t b0, uint32_t b1) {
    asm volatile(
        "mma.sync.aligned.m16n8k8.row.col.f32.tf32.tf32.f32 "
        "{%0,%1,%2,%3}, {%4,%5,%6,%7}, {%8,%9}, {%0,%1,%2,%3};"
        : "+f"(c[0]), "+f"(c[1]), "+f"(c[2]), "+f"(c[3])
        : "r"(a0), "r"(a1), "r"(a2), "r"(a3), "r"(b0), "r"(b1));
}
// within each 8-k group, place (k, k+4) adjacent: pos = (k&3)*2 + ((k>>2)&1)
__device__ __forceinline__ int kperm(int k) {
    return (k & ~7) + ((k & 3) * 2) + ((k >> 2) & 1);
}

// ---------------------------------------------------------------------------
// K0: transpose + tf32-round + k-permute weights.
// ---------------------------------------------------------------------------
__global__ void transpose_w_kernel(const float* __restrict__ wqkv,
                                   const float* __restrict__ wout,
                                   float* __restrict__ wT)
{
    const int i = blockIdx.x * 256 + threadIdx.x;
    if (i < 49152) {
        const int k = i / 384, n = i - k * 384;
        wT[n * 128 + kperm(k)] = to_tf32(wqkv[i]);
    }
    if (i < 16384) {
        const int k = i >> 7, n = i & 127;
        wT[49152 + n * 128 + kperm(k)] = to_tf32(wout[i]);
    }
}

// ---------------------------------------------------------------------------
// KF: fully fused per-window kernel. 1 CTA = 1 window, 256 threads (8 warps).
// Phases: A) LN+gather -> xs  B) QKV GEMM (3 passes, B from L2)
//         C) attention (warp = head, rowhalf loop; O kept in regs)
//         D) O -> os smem tile; out-proj GEMM pass; window-merge scatter.
// ---------------------------------------------------------------------------
__global__ void __launch_bounds__(256, 2)
fused_all_kernel(const float* __restrict__ x,
                 const float* __restrict__ WT,     // [384+128][128] tf32 k-permuted
                 const float* __restrict__ bqkv,   // [384]
                 const float* __restrict__ bout,   // [128]
                 const float* __restrict__ gamma,
                 const float* __restrict__ beta,
                 float* __restrict__ out)
{
    extern __shared__ float smd[];
    float* xs = smd;                              // [64][132]
    const int g    = blockIdx.x;                  // window
    const int tid  = threadIdx.x;
    const int warp = tid >> 5;                    // head / GEMM warp
    const int lane = tid & 31;
    const int qrow = lane >> 2;
    const int qcol = lane & 3;

    float* qs_h = smd + REG2_OFF + warp * 1960;   // [49][20]
    float* ks_h = qs_h + 980;                     // [49][20]
    float* vt_h = smd + warp * 960;               // [16][60], aliases xs
    float* os   = smd + REG2_OFF;                 // [64][132], aliases qs/ks (phase D)

    const int b = g >> 6, w = g & 63;

    // ---- Phase A: gather + LayerNorm -> xs rows 0..48 (tf32-rounded) ----
    {
        float4 gm = reinterpret_cast<const float4*>(gamma)[lane];
        float4 bt = reinterpret_cast<const float4*>(beta)[lane];
        const float4* X4 = reinterpret_cast<const float4*>(x);
        for (int p = warp; p < 49; p += 8) {
            const int row = (w >> 3) * 7 + p / 7;
            const int col = (w & 7) * 7 + p % 7;
            float4 v = X4[((size_t)b * 3136 + row * 56 + col) * 32 + lane];
            float sum = v.x + v.y + v.z + v.w;
            #pragma unroll
            for (int o = 16; o > 0; o >>= 1) sum += __shfl_xor_sync(0xffffffffu, sum, o);
            const float mu = sum * (1.0f / 128.0f);
            float4 d;
            d.x = v.x - mu; d.y = v.y - mu; d.z = v.z - mu; d.w = v.w - mu;
            float sq = d.x * d.x + d.y * d.y + d.z * d.z + d.w * d.w;
            #pragma unroll
            for (int o = 16; o > 0; o >>= 1) sq += __shfl_xor_sync(0xffffffffu, sq, o);
            const float rstd = rsqrtf(sq * (1.0f / 128.0f) + LN_EPS);
            v.x = to_tf32(d.x * rstd * gm.x + bt.x);
            v.y = to_tf32(d.y * rstd * gm.y + bt.y);
            v.z = to_tf32(d.z * rstd * gm.z + bt.z);
            v.w = to_tf32(d.w * rstd * gm.w + bt.w);
            *reinterpret_cast<float4*>(&xs[p * XS_LDA + lane * 4]) = v;
        }
    }
    __syncthreads();

    // ---- Phase B: QKV GEMM, 3 passes (q, k, v) ----
    #pragma unroll 1
    for (int pass = 0; pass < 3; pass++) {
        const float* wp = WT + (size_t)(pass * 128 + warp * 16) * 128;

        float acc[4][2][4];
        #pragma unroll
        for (int i = 0; i < 4; i++)
            #pragma unroll
            for (int j = 0; j < 2; j++)
                #pragma unroll
                for (int r = 0; r < 4; r++) acc[i][j][r] = 0.0f;

        #pragma unroll
        for (int ch = 0; ch < 2; ch++) {
            float2 bb[8][2];
            #pragma unroll
            for (int s = 0; s < 8; s++) {
                const int kk = ch * 64 + s * 8;
                bb[s][0] = *reinterpret_cast<const float2*>(wp + qrow * 128 + kk + 2 * qcol);
                bb[s][1] = *reinterpret_cast<const float2*>(wp + (8 + qrow) * 128 + kk + 2 * qcol);
            }
            #pragma unroll
            for (int s = 0; s < 8; s++) {
                const int kk = ch * 64 + s * 8;
                #pragma unroll
                for (int i = 0; i < 4; i++) {
                    const float* ap = xs + (i * 16 + qrow) * XS_LDA + kk + qcol;
                    const uint32_t a0 = __float_as_uint(ap[0]);
                    const uint32_t a1 = __float_as_uint(ap[8 * XS_LDA]);
                    const uint32_t a2 = __float_as_uint(ap[4]);
                    const uint32_t a3 = __float_as_uint(ap[8 * XS_LDA + 4]);
                    mma_tf32(acc[i][0], a0, a1, a2, a3,
                             __float_as_uint(bb[s][0].x), __float_as_uint(bb[s][0].y));
                    mma_tf32(acc[i][1], a0, a1, a2, a3,
                             __float_as_uint(bb[s][1].x), __float_as_uint(bb[s][1].y));
                }
            }
        }

        // before v epilogue (vt aliases xs) all warps must be done reading xs
        if (pass == 2) __syncthreads();

        #pragma unroll
        for (int i = 0; i < 4; i++) {
            #pragma unroll
            for (int half = 0; half < 2; half++) {
                const int r = i * 16 + qrow + half * 8;
                if (r < 49) {
                    #pragma unroll
                    for (int j = 0; j < 2; j++) {
                        const int d = j * 8 + 2 * qcol;
                        const int bidx = pass * 128 + warp * 16 + d;
                        float vx = acc[i][j][half * 2 + 0] + __ldg(&bqkv[bidx]);
                        float vy = acc[i][j][half * 2 + 1] + __ldg(&bqkv[bidx + 1]);
                        if (pass == 0) {
                            float2 v; v.x = vx * SCALE_ATT; v.y = vy * SCALE_ATT;
                            *reinterpret_cast<float2*>(&qs_h[r * 20 + d]) = v;
                        } else if (pass == 1) {
                            float2 v; v.x = vx; v.y = vy;
                            *reinterpret_cast<float2*>(&ks_h[r * 20 + d]) = v;
                        } else {
                            vt_h[d * 60 + r] = vx;
                            vt_h[(d + 1) * 60 + r] = vy;
                        }
                    }
                }
            }
        }
    }

    // zero vt pad cols 49..59 (read by PV k-tile 6)
    for (int i2 = lane; i2 < 176; i2 += 32) {
        const int d = i2 / 11, c = 49 + i2 % 11;
        vt_h[d * 60 + c] = 0.0f;
    }
    __syncwarp();

    // ---- Phase C: attention (warp = head), O kept in registers ----
    float oall[2][2][2][4];                       // [rowhalf][i][jn][r], pre-scaled

    #pragma unroll 1
    for (int rowhalf = 0; rowhalf < 2; rowhalf++) {
        float sc[2][7][4];
        #pragma unroll
        for (int i = 0; i < 2; i++)
            #pragma unroll
            for (int j = 0; j < 7; j++)
                #pragma unroll
                for (int r = 0; r < 4; r++) sc[i][j][r] = 0.0f;

        #pragma unroll
        for (int ks = 0; ks < 2; ks++) {
            const int kk = ks * 8;
            uint32_t ah[2][4];
            #pragma unroll
            for (int i = 0; i < 2; i++) {
                const int it = rowhalf * 2 + i;
                const float* ap = qs_h + (it * 16 + qrow) * 20 + kk + qcol;
                ah[i][0] = __float_as_uint(to_tf32(ap[0]));
                ah[i][1] = __float_as_uint(to_tf32(ap[160]));
                ah[i][2] = __float_as_uint(to_tf32(ap[4]));
                ah[i][3] = __float_as_uint(to_tf32(ap[164]));
            }
            #pragma unroll
            for (int j = 0; j < 7; j++) {
                const float* bp = ks_h + (j * 8 + qrow) * 20 + kk + qcol;
                const uint32_t Bh0 = __float_as_uint(to_tf32(bp[0]));
                const uint32_t Bh1 = __float_as_uint(to_tf32(bp[4]));
                #pragma unroll
                for (int i = 0; i < 2; i++)
                    mma_tf32(sc[i][j], ah[i][0], ah[i][1], ah[i][2], ah[i][3], Bh0, Bh1);
            }
        }

        float invlo[2], invhi[2];
        #pragma unroll
        for (int i = 0; i < 2; i++) {
            if (qcol != 0) { sc[i][6][0] = -1e30f; sc[i][6][2] = -1e30f; }
            sc[i][6][1] = -1e30f; sc[i][6][3] = -1e30f;

            float mlo = -1e30f, mhi = -1e30f;
            #pragma unroll
            for (int j = 0; j < 7; j++) {
                mlo = fmaxf(mlo, fmaxf(sc[i][j][0], sc[i][j][1]));
                mhi = fmaxf(mhi, fmaxf(sc[i][j][2], sc[i][j][3]));
            }
            mlo = fmaxf(mlo, __shfl_xor_sync(0xffffffffu, mlo, 1));
            mlo = fmaxf(mlo, __shfl_xor_sync(0xffffffffu, mlo, 2));
            mhi = fmaxf(mhi, __shfl_xor_sync(0xffffffffu, mhi, 1));
            mhi = fmaxf(mhi, __shfl_xor_sync(0xffffffffu, mhi, 2));

            float slo = 0.0f, shi = 0.0f;
            #pragma unroll
            for (int j = 0; j < 7; j++) {
                sc[i][j][0] = __expf(sc[i][j][0] - mlo);
                sc[i][j][1] = __expf(sc[i][j][1] - mlo);
                sc[i][j][2] = __expf(sc[i][j][2] - mhi);
                sc[i][j][3] = __expf(sc[i][j][3] - mhi);
                slo += sc[i][j][0] + sc[i][j][1];
                shi += sc[i][j][2] + sc[i][j][3];
            }
            slo += __shfl_xor_sync(0xffffffffu, slo, 1);
            slo += __shfl_xor_sync(0xffffffffu, slo, 2);
            shi += __shfl_xor_sync(0xffffffffu, shi, 1);
            shi += __shfl_xor_sync(0xffffffffu, shi, 2);
            invlo[i] = 1.0f / slo;
            invhi[i] = 1.0f / shi;
        }

        float oacc[2][2][4];
        #pragma unroll
        for (int i = 0; i < 2; i++)
            #pragma unroll
            for (int jn = 0; jn < 2; jn++)
                #pragma unroll
                for (int r = 0; r < 4; r++) oacc[i][jn][r] = 0.0f;

        const unsigned src0 = (lane & 28) | (qcol >> 1);
        const unsigned src1 = src0 + 2;
        const bool odd = (qcol & 1) != 0;

        #pragma unroll
        for (int kt = 0; kt < 7; kt++) {
            uint32_t Bh[2][2];
            #pragma unroll
            for (int jn = 0; jn < 2; jn++) {
                const float* bp = vt_h + (jn * 8 + qrow) * 60 + kt * 8 + qcol;
                Bh[jn][0] = __float_as_uint(to_tf32(bp[0]));
                Bh[jn][1] = __float_as_uint(to_tf32(bp[4]));
            }
            #pragma unroll
            for (int i = 0; i < 2; i++) {
                float t0 = __shfl_sync(0xffffffffu, sc[i][kt][0], src0);
                float t1 = __shfl_sync(0xffffffffu, sc[i][kt][1], src0);
                float u0 = __shfl_sync(0xffffffffu, sc[i][kt][0], src1);
                float u1 = __shfl_sync(0xffffffffu, sc[i][kt][1], src1);
                float t2 = __shfl_sync(0xffffffffu, sc[i][kt][2], src0);
                float t3 = __shfl_sync(0xffffffffu, sc[i][kt][3], src0);
                float u2 = __shfl_sync(0xffffffffu, sc[i][kt][2], src1);
                float u3 = __shfl_sync(0xffffffffu, sc[i][kt][3], src1);
                const uint32_t Ah0 = __float_as_uint(to_tf32(odd ? t1 : t0));
                const uint32_t Ah1 = __float_as_uint(to_tf32(odd ? t3 : t2));
                const uint32_t Ah2 = __float_as_uint(to_tf32(odd ? u1 : u0));
                const uint32_t Ah3 = __float_as_uint(to_tf32(odd ? u3 : u2));
                #pragma unroll
                for (int jn = 0; jn < 2; jn++)
                    mma_tf32(oacc[i][jn], Ah0, Ah1, Ah2, Ah3, Bh[jn][0], Bh[jn][1]);
            }
        }

        // fold 1/rowsum, keep in regs (tf32-round at the os store below)
        #pragma unroll
        for (int i = 0; i < 2; i++)
            #pragma unroll
            for (int jn = 0; jn < 2; jn++) {
                oall[rowhalf][i][jn][0] = oacc[i][jn][0] * invlo[i];
                oall[rowhalf][i][jn][1] = oacc[i][jn][1] * invlo[i];
                oall[rowhalf][i][jn][2] = oacc[i][jn][2] * invhi[i];
                oall[rowhalf][i][jn][3] = oacc[i][jn][3] * invhi[i];
            }
    }

    // ---- Phase D: O -> os tile (aliases qs/ks), then out-proj GEMM ----
    __syncthreads();   // all warps done reading qs/ks before os overwrites

    #pragma unroll
    for (int rowhalf = 0; rowhalf < 2; rowhalf++)
        #pragma unroll
        for (int i = 0; i < 2; i++) {
            const int it = rowhalf * 2 + i;
            const int rlo = it * 16 + qrow;
            const int rhi = rlo + 8;
            #pragma unroll
            for (int jn = 0; jn < 2; jn++) {
                const int d = warp * 16 + jn * 8 + 2 * qcol;
                if (rlo < 49) {
                    float2 v;
                    v.x = to_tf32(oall[rowhalf][i][jn][0]);
                    v.y = to_tf32(oall[rowhalf][i][jn][1]);
                    *reinterpret_cast<float2*>(&os[rlo * XS_LDA + d]) = v;
                }
                if (rhi < 49) {
                    float2 v;
                    v.x = to_tf32(oall[rowhalf][i][jn][2]);
                    v.y = to_tf32(oall[rowhalf][i][jn][3]);
                    *reinterpret_cast<float2*>(&os[rhi * XS_LDA + d]) = v;
                }
            }
        }
    // zero pad rows 49..63
    for (int i2 = tid; i2 < 15 * XS_LDA; i2 += 256) os[49 * XS_LDA + i2] = 0.0f;
    __syncthreads();

    // proj GEMM: A = os, B = wT_out (L2), warp cols warp*16..+15
    {
        const float* wp = WT + 49152 + (size_t)(warp * 16) * 128;

        float acc[4][2][4];
        #pragma unroll
        for (int i = 0; i < 4; i++)
            #pragma unroll
            for (int j = 0; j < 2; j++)
                #pragma unroll
                for (int r = 0; r < 4; r++) acc[i][j][r] = 0.0f;

        #pragma unroll
        for (int ch = 0; ch < 2; ch++) {
            float2 bb[8][2];
            #pragma unroll
            for (int s = 0; s < 8; s++) {
                const int kk = ch * 64 + s * 8;
                bb[s][0] = *reinterpret_cast<const float2*>(wp + qrow * 128 + kk + 2 * qcol);
                bb[s][1] = *reinterpret_cast<const float2*>(wp + (8 + qrow) * 128 + kk + 2 * qcol);
            }
            #pragma unroll
            for (int s = 0; s < 8; s++) {
                const int kk = ch * 64 + s * 8;
                #pragma unroll
                for (int i = 0; i < 4; i++) {
                    const float* ap = os + (i * 16 + qrow) * XS_LDA + kk + qcol;
                    const uint32_t a0 = __float_as_uint(ap[0]);
                    const uint32_t a1 = __float_as_uint(ap[8 * XS_LDA]);
                    const uint32_t a2 = __float_as_uint(ap[4]);
                    const uint32_t a3 = __float_as_uint(ap[8 * XS_LDA + 4]);
                    mma_tf32(acc[i][0], a0, a1, a2, a3,
                             __float_as_uint(bb[s][0].x), __float_as_uint(bb[s][0].y));
                    mma_tf32(acc[i][1], a0, a1, a2, a3,
                             __float_as_uint(bb[s][1].x), __float_as_uint(bb[s][1].y));
                }
            }
        }

        // epilogue: +bias, window-merge scatter to d_out
        #pragma unroll
        for (int i = 0; i < 4; i++) {
            #pragma unroll
            for (int half = 0; half < 2; half++) {
                const int p = i * 16 + qrow + half * 8;
                if (p < 49) {
                    const int row = (w >> 3) * 7 + p / 7;
                    const int col = (w & 7) * 7 + p % 7;
                    float* op = out + ((size_t)b * 3136 + row * 56 + col) * 128;
                    #pragma unroll
                    for (int j = 0; j < 2; j++) {
                        const int cofs = warp * 16 + j * 8 + 2 * qcol;
                        float2 v;
                        v.x = acc[i][j][half * 2 + 0] + __ldg(&bout[cofs]);
                        v.y = acc[i][j][half * 2 + 1] + __ldg(&bout[cofs + 1]);
                        *reinterpret_cast<float2*>(op + cofs) = v;
                    }
                }
            }
        }
    }
}

// ---------------------------------------------------------------------------
// Launch
// ---------------------------------------------------------------------------
extern "C" void kernel_launch(void* const* d_in, const int* in_sizes, int n_in,
                              void* d_out, int out_size)
{
    const float* x       = (const float*)d_in[0];
    const float* ln_g    = (const float*)d_in[1];
    const float* ln_b    = (const float*)d_in[2];
    const float* w_qkv   = (const float*)d_in[3];
    const float* b_qkv   = (const float*)d_in[4];
    const float* w_out   = (const float*)d_in[5];
    const float* b_out   = (const float*)d_in[6];
    float* out           = (float*)d_out;

    void* wT_ptr = nullptr;
    cudaGetSymbolAddress(&wT_ptr, g_wT);
    float* wT = (float*)wT_ptr;

    cudaFuncSetAttribute((const void*)fused_all_kernel,
                         cudaFuncAttributeMaxDynamicSharedMemorySize, FUSED_SMEM);

    // K0: weight transpose + tf32 round + k-permute (tiny)
    transpose_w_kernel<<<192, 256>>>(w_qkv, w_out, wT);

    // KF: fully fused LN + partition + QKV + attention + proj + merge
    fused_all_kernel<<<4096, 256, FUSED_SMEM>>>(x, wT, b_qkv, b_out, ln_g, ln_b, out);
}

// round 16
// speedup vs baseline: 1.3054x; 1.3054x over previous
#include <cuda_runtime.h>
#include <cuda_fp16.h>
#include <cstdint>

// ---------------------------------------------------------------------------
// Window-based self-attention (Swin-style), B=64, 56x56, C=128, WS=7, NH=8.
// Round 16: pipeline converted to fp16 mma (m16n8k16). Same 10-bit mantissa
// as tf32 -> same error budget, but: mma count halved, LDS/LDG bytes halved,
// PV C->A shuffle transform eliminated (fp16 A-frag == C-frag pairs).
//   K0: weights -> fp16, transposed (natural k-pairs; no permute)
//   KF: fused LN + partition + QKV GEMM + attention + out-proj + merge
// smem 57KB, 2 CTAs/SM.
// ---------------------------------------------------------------------------

#define SCALE_ATT 0.25f             // HD^-0.5, HD=16
#define LN_EPS    1e-5f

#define XS_LDAH   136               // xs/os row stride (halves): 4*qrow+qcol banks
#define QK_LDAH   24                // q/k slab row stride (halves): 12*qrow+qcol
#define VT_LDAH   72                // vt row stride (halves): 4*d+qcol
#define R1_OFF    9216              // halves: start of q/k slabs (= 8*16*72 vt region)
#define SLAB_H    2352              // halves per head slab (q 49*24 + k 49*24)
#define FUSED_SMEM ((9216 + 8 * 2352 + 512) * 2)   // 57088 B

__device__ __half g_wH[(384 + 128) * 128];   // fp16 wT_qkv | wT_out

// ---------------------------------------------------------------------------
// helpers
// ---------------------------------------------------------------------------
__device__ __forceinline__ uint32_t pack_h2(float lo, float hi) {
    uint32_t d;
    asm("cvt.rn.f16x2.f32 %0, %1, %2;" : "=r"(d) : "f"(hi), "f"(lo));
    return d;
}
__device__ __forceinline__ void mma_f16(float* c,
                                        uint32_t a0, uint32_t a1, uint32_t a2, uint32_t a3,
                                        uint32_t b0, uint32_t b1) {
    asm volatile(
        "mma.sync.aligned.m16n8k16.row.col.f32.f16.f16.f32 "
        "{%0,%1,%2,%3}, {%4,%5,%6,%7}, {%8,%9}, {%0,%1,%2,%3};"
        : "+f"(c[0]), "+f"(c[1]), "+f"(c[2]), "+f"(c[3])
        : "r"(a0), "r"(a1), "r"(a2), "r"(a3), "r"(b0), "r"(b1));
}
__device__ __forceinline__ uint32_t ldsm_u32(const __half* p) {
    return *reinterpret_cast<const uint32_t*>(p);
}

// ---------------------------------------------------------------------------
// K0: weights -> fp16 transposed. wT[n][k] with k contiguous (natural pairs).
// ---------------------------------------------------------------------------
__global__ void prep_w_kernel(const float* __restrict__ wqkv,
                              const float* __restrict__ wout,
                              __half* __restrict__ wH)
{
    const int i = blockIdx.x * 256 + threadIdx.x;
    if (i < 49152) {
        const int k = i / 384, n = i - k * 384;
        wH[n * 128 + k] = __float2half_rn(wqkv[i]);
    }
    if (i < 16384) {
        const int k = i >> 7, n = i & 127;
        wH[49152 + n * 128 + k] = __float2half_rn(wout[i]);
    }
}

// ---------------------------------------------------------------------------
// KF: fully fused per-window kernel. 1 CTA = 1 window, 256 threads (8 warps).
// ---------------------------------------------------------------------------
__global__ void __launch_bounds__(256, 2)
fused_all_kernel(const float* __restrict__ x,
                 const __half* __restrict__ wH,    // [384+128][128] fp16
                 const float* __restrict__ bqkv,   // [384]
                 const float* __restrict__ bout,   // [128]
                 const float* __restrict__ gamma,
                 const float* __restrict__ beta,
                 float* __restrict__ out)
{
    extern __shared__ __half smh[];
    __half* xs = smh;                              // [64][136]
    const int g    = blockIdx.x;                   // window
    const int tid  = threadIdx.x;
    const int warp = tid >> 5;                     // head / GEMM warp
    const int lane = tid & 31;
    const int qrow = lane >> 2;
    const int qcol = lane & 3;

    __half* qs_h = smh + R1_OFF + warp * SLAB_H;   // [49][24]
    __half* ks_h = qs_h + 49 * QK_LDAH;            // [49][24]
    __half* vt_h = smh + warp * (16 * VT_LDAH);    // [16][72], aliases xs
    __half* os   = smh + R1_OFF;                   // [64][136], aliases qs/ks

    const int b = g >> 6, w = g & 63;

    // ---- Phase A: gather + LayerNorm -> xs rows 0..48 (fp16) ----
    {
        float4 gm = reinterpret_cast<const float4*>(gamma)[lane];
        float4 bt = reinterpret_cast<const float4*>(beta)[lane];
        const float4* X4 = reinterpret_cast<const float4*>(x);
        for (int p = warp; p < 49; p += 8) {
            const int row = (w >> 3) * 7 + p / 7;
            const int col = (w & 7) * 7 + p % 7;
            float4 v = X4[((size_t)b * 3136 + row * 56 + col) * 32 + lane];
            float sum = v.x + v.y + v.z + v.w;
            #pragma unroll
            for (int o = 16; o > 0; o >>= 1) sum += __shfl_xor_sync(0xffffffffu, sum, o);
            const float mu = sum * (1.0f / 128.0f);
            float4 d;
            d.x = v.x - mu; d.y = v.y - mu; d.z = v.z - mu; d.w = v.w - mu;
            float sq = d.x * d.x + d.y * d.y + d.z * d.z + d.w * d.w;
            #pragma unroll
            for (int o = 16; o > 0; o >>= 1) sq += __shfl_xor_sync(0xffffffffu, sq, o);
            const float rstd = rsqrtf(sq * (1.0f / 128.0f) + LN_EPS);
            uint2 hv;
            hv.x = pack_h2(d.x * rstd * gm.x + bt.x, d.y * rstd * gm.y + bt.y);
            hv.y = pack_h2(d.z * rstd * gm.z + bt.z, d.w * rstd * gm.w + bt.w);
            *reinterpret_cast<uint2*>(&xs[p * XS_LDAH + lane * 4]) = hv;
        }
    }
    __syncthreads();

    // ---- Phase B: QKV GEMM, 3 passes (q, k, v) ----
    #pragma unroll 1
    for (int pass = 0; pass < 3; pass++) {
        const __half* wp = wH + (size_t)(pass * 128 + warp * 16) * 128;

        float acc[4][2][4];
        #pragma unroll
        for (int i = 0; i < 4; i++)
            #pragma unroll
            for (int j = 0; j < 2; j++)
                #pragma unroll
                for (int r = 0; r < 4; r++) acc[i][j][r] = 0.0f;

        // prefetch all B frags (K=128 = 8 k16-steps), L2-hot
        uint32_t bb[8][2][2];
        #pragma unroll
        for (int s = 0; s < 8; s++)
            #pragma unroll
            for (int j = 0; j < 2; j++) {
                const __half* bp = wp + (j * 8 + qrow) * 128 + 16 * s + 2 * qcol;
                bb[s][j][0] = ldsm_u32(bp);
                bb[s][j][1] = ldsm_u32(bp + 8);
            }

        #pragma unroll
        for (int s = 0; s < 8; s++) {
            #pragma unroll
            for (int i = 0; i < 4; i++) {
                const __half* ap = xs + (i * 16 + qrow) * XS_LDAH + 16 * s + 2 * qcol;
                const uint32_t a0 = ldsm_u32(ap);
                const uint32_t a1 = ldsm_u32(ap + 8 * XS_LDAH);
                const uint32_t a2 = ldsm_u32(ap + 8);
                const uint32_t a3 = ldsm_u32(ap + 8 * XS_LDAH + 8);
                mma_f16(acc[i][0], a0, a1, a2, a3, bb[s][0][0], bb[s][0][1]);
                mma_f16(acc[i][1], a0, a1, a2, a3, bb[s][1][0], bb[s][1][1]);
            }
        }

        // before v epilogue (vt aliases xs) all warps must be done reading xs
        if (pass == 2) __syncthreads();

        #pragma unroll
        for (int i = 0; i < 4; i++) {
            #pragma unroll
            for (int half = 0; half < 2; half++) {
                const int r = i * 16 + qrow + half * 8;
                if (r < 49) {
                    #pragma unroll
                    for (int j = 0; j < 2; j++) {
                        const int d = j * 8 + 2 * qcol;
                        const int bidx = pass * 128 + warp * 16 + d;
                        const float vx = acc[i][j][half * 2 + 0] + __ldg(&bqkv[bidx]);
                        const float vy = acc[i][j][half * 2 + 1] + __ldg(&bqkv[bidx + 1]);
                        if (pass == 0) {
                            *reinterpret_cast<uint32_t*>(&qs_h[r * QK_LDAH + d]) =
                                pack_h2(vx * SCALE_ATT, vy * SCALE_ATT);
                        } else if (pass == 1) {
                            *reinterpret_cast<uint32_t*>(&ks_h[r * QK_LDAH + d]) =
                                pack_h2(vx, vy);
                        } else {
                            vt_h[d * VT_LDAH + r]       = __float2half_rn(vx);
                            vt_h[(d + 1) * VT_LDAH + r] = __float2half_rn(vy);
                        }
                    }
                }
            }
        }
    }

    // zero vt pad cols 49..63 (PV reads up to c=63)
    for (int i2 = lane; i2 < 240; i2 += 32) {
        const int d = i2 / 15, c = 49 + i2 % 15;
        vt_h[d * VT_LDAH + c] = __ushort_as_half((unsigned short)0);
    }
    __syncwarp();

    // ---- Phase C: attention (warp = head), O kept in registers ----
    float oall[2][2][2][4];                        // [rowhalf][i][jn][r], pre-scaled

    #pragma unroll 1
    for (int rowhalf = 0; rowhalf < 2; rowhalf++) {
        // scores: S = Q K^T — single k16 step
        float sc[2][7][4];
        #pragma unroll
        for (int i = 0; i < 2; i++)
            #pragma unroll
            for (int j = 0; j < 7; j++)
                #pragma unroll
                for (int r = 0; r < 4; r++) sc[i][j][r] = 0.0f;

        uint32_t ah[2][4];
        #pragma unroll
        for (int i = 0; i < 2; i++) {
            const int it = rowhalf * 2 + i;
            const __half* ap = qs_h + (it * 16 + qrow) * QK_LDAH + 2 * qcol;
            ah[i][0] = ldsm_u32(ap);
            ah[i][1] = ldsm_u32(ap + 8 * QK_LDAH);
            ah[i][2] = ldsm_u32(ap + 8);
            ah[i][3] = ldsm_u32(ap + 8 * QK_LDAH + 8);
        }
        #pragma unroll
        for (int j = 0; j < 7; j++) {
            const __half* bp = ks_h + (j * 8 + qrow) * QK_LDAH + 2 * qcol;
            const uint32_t b0 = ldsm_u32(bp);
            const uint32_t b1 = ldsm_u32(bp + 8);
            #pragma unroll
            for (int i = 0; i < 2; i++)
                mma_f16(sc[i][j], ah[i][0], ah[i][1], ah[i][2], ah[i][3], b0, b1);
        }

        // softmax in C layout
        float invlo[2], invhi[2];
        #pragma unroll
        for (int i = 0; i < 2; i++) {
            if (qcol != 0) { sc[i][6][0] = -1e30f; sc[i][6][2] = -1e30f; }
            sc[i][6][1] = -1e30f; sc[i][6][3] = -1e30f;

            float mlo = -1e30f, mhi = -1e30f;
            #pragma unroll
            for (int j = 0; j < 7; j++) {
                mlo = fmaxf(mlo, fmaxf(sc[i][j][0], sc[i][j][1]));
                mhi = fmaxf(mhi, fmaxf(sc[i][j][2], sc[i][j][3]));
            }
            mlo = fmaxf(mlo, __shfl_xor_sync(0xffffffffu, mlo, 1));
            mlo = fmaxf(mlo, __shfl_xor_sync(0xffffffffu, mlo, 2));
            mhi = fmaxf(mhi, __shfl_xor_sync(0xffffffffu, mhi, 1));
            mhi = fmaxf(mhi, __shfl_xor_sync(0xffffffffu, mhi, 2));

            float slo = 0.0f, shi = 0.0f;
            #pragma unroll
            for (int j = 0; j < 7; j++) {
                sc[i][j][0] = __expf(sc[i][j][0] - mlo);
                sc[i][j][1] = __expf(sc[i][j][1] - mlo);
                sc[i][j][2] = __expf(sc[i][j][2] - mhi);
                sc[i][j][3] = __expf(sc[i][j][3] - mhi);
                slo += sc[i][j][0] + sc[i][j][1];
                shi += sc[i][j][2] + sc[i][j][3];
            }
            slo += __shfl_xor_sync(0xffffffffu, slo, 1);
            slo += __shfl_xor_sync(0xffffffffu, slo, 2);
            shi += __shfl_xor_sync(0xffffffffu, shi, 1);
            shi += __shfl_xor_sync(0xffffffffu, shi, 2);
            invlo[i] = 1.0f / slo;
            invhi[i] = 1.0f / shi;
        }

        // PV: O = P V. fp16 A-frags are exactly the C-frag pairs — no shuffles.
        float oacc[2][2][4];
        #pragma unroll
        for (int i = 0; i < 2; i++)
            #pragma unroll
            for (int jn = 0; jn < 2; jn++)
                #pragma unroll
                for (int r = 0; r < 4; r++) oacc[i][jn][r] = 0.0f;

        #pragma unroll
        for (int kt = 0; kt < 4; kt++) {
            uint32_t Bh[2][2];
            #pragma unroll
            for (int jn = 0; jn < 2; jn++) {
                const __half* bp = vt_h + (jn * 8 + qrow) * VT_LDAH + kt * 16 + 2 * qcol;
                Bh[jn][0] = ldsm_u32(bp);
                Bh[jn][1] = ldsm_u32(bp + 8);
            }
            #pragma unroll
            for (int i = 0; i < 2; i++) {
                const uint32_t a0 = pack_h2(sc[i][2 * kt][0], sc[i][2 * kt][1]);
                const uint32_t a1 = pack_h2(sc[i][2 * kt][2], sc[i][2 * kt][3]);
                const uint32_t a2 = (kt < 3) ? pack_h2(sc[i][2 * kt + 1][0], sc[i][2 * kt + 1][1]) : 0u;
                const uint32_t a3 = (kt < 3) ? pack_h2(sc[i][2 * kt + 1][2], sc[i][2 * kt + 1][3]) : 0u;
                #pragma unroll
                for (int jn = 0; jn < 2; jn++)
                    mma_f16(oacc[i][jn], a0, a1, a2, a3, Bh[jn][0], Bh[jn][1]);
            }
        }

        #pragma unroll
        for (int i = 0; i < 2; i++)
            #pragma unroll
            for (int jn = 0; jn < 2; jn++) {
                oall[rowhalf][i][jn][0] = oacc[i][jn][0] * invlo[i];
                oall[rowhalf][i][jn][1] = oacc[i][jn][1] * invlo[i];
                oall[rowhalf][i][jn][2] = oacc[i][jn][2] * invhi[i];
                oall[rowhalf][i][jn][3] = oacc[i][jn][3] * invhi[i];
            }
    }

    // ---- Phase D: O -> os tile (aliases qs/ks), then out-proj GEMM ----
    __syncthreads();   // all warps done reading qs/ks before os overwrites

    #pragma unroll
    for (int rowhalf = 0; rowhalf < 2; rowhalf++)
        #pragma unroll
        for (int i = 0; i < 2; i++) {
            const int it = rowhalf * 2 + i;
            const int rlo = it * 16 + qrow;
            const int rhi = rlo + 8;
            #pragma unroll
            for (int jn = 0; jn < 2; jn++) {
                const int d = warp * 16 + jn * 8 + 2 * qcol;
                if (rlo < 49)
                    *reinterpret_cast<uint32_t*>(&os[rlo * XS_LDAH + d]) =
                        pack_h2(oall[rowhalf][i][jn][0], oall[rowhalf][i][jn][1]);
                if (rhi < 49)
                    *reinterpret_cast<uint32_t*>(&os[rhi * XS_LDAH + d]) =
                        pack_h2(oall[rowhalf][i][jn][2], oall[rowhalf][i][jn][3]);
            }
        }
    // zero pad rows 49..63
    for (int i2 = tid; i2 < 15 * XS_LDAH; i2 += 256)
        os[49 * XS_LDAH + i2] = __ushort_as_half((unsigned short)0);
    __syncthreads();

    // proj GEMM: A = os, B = wT_out (L2), warp cols warp*16..+15
    {
        const __half* wp = wH + 49152 + (size_t)(warp * 16) * 128;

        float acc[4][2][4];
        #pragma unroll
        for (int i = 0; i < 4; i++)
            #pragma unroll
            for (int j = 0; j < 2; j++)
                #pragma unroll
                for (int r = 0; r < 4; r++) acc[i][j][r] = 0.0f;

        uint32_t bb[8][2][2];
        #pragma unroll
        for (int s = 0; s < 8; s++)
            #pragma unroll
            for (int j = 0; j < 2; j++) {
                const __half* bp = wp + (j * 8 + qrow) * 128 + 16 * s + 2 * qcol;
                bb[s][j][0] = ldsm_u32(bp);
                bb[s][j][1] = ldsm_u32(bp + 8);
            }

        #pragma unroll
        for (int s = 0; s < 8; s++) {
            #pragma unroll
            for (int i = 0; i < 4; i++) {
                const __half* ap = os + (i * 16 + qrow) * XS_LDAH + 16 * s + 2 * qcol;
                const uint32_t a0 = ldsm_u32(ap);
                const uint32_t a1 = ldsm_u32(ap + 8 * XS_LDAH);
                const uint32_t a2 = ldsm_u32(ap + 8);
                const uint32_t a3 = ldsm_u32(ap + 8 * XS_LDAH + 8);
                mma_f16(acc[i][0], a0, a1, a2, a3, bb[s][0][0], bb[s][0][1]);
                mma_f16(acc[i][1], a0, a1, a2, a3, bb[s][1][0], bb[s][1][1]);
            }
        }

        // epilogue: +bias, window-merge scatter to d_out (f32)
        #pragma unroll
        for (int i = 0; i < 4; i++) {
            #pragma unroll
            for (int half = 0; half < 2; half++) {
                const int p = i * 16 + qrow + half * 8;
                if (p < 49) {
                    const int row = (w >> 3) * 7 + p / 7;
                    const int col = (w & 7) * 7 + p % 7;
                    float* op = out + ((size_t)b * 3136 + row * 56 + col) * 128;
                    #pragma unroll
                    for (int j = 0; j < 2; j++) {
                        const int cofs = warp * 16 + j * 8 + 2 * qcol;
                        float2 v;
                        v.x = acc[i][j][half * 2 + 0] + __ldg(&bout[cofs]);
                        v.y = acc[i][j][half * 2 + 1] + __ldg(&bout[cofs + 1]);
                        *reinterpret_cast<float2*>(op + cofs) = v;
                    }
                }
            }
        }
    }
}

// ---------------------------------------------------------------------------
// Launch
// ---------------------------------------------------------------------------
extern "C" void kernel_launch(void* const* d_in, const int* in_sizes, int n_in,
                              void* d_out, int out_size)
{
    const float* x       = (const float*)d_in[0];
    const float* ln_g    = (const float*)d_in[1];
    const float* ln_b    = (const float*)d_in[2];
    const float* w_qkv   = (const float*)d_in[3];
    const float* b_qkv   = (const float*)d_in[4];
    const float* w_out   = (const float*)d_in[5];
    const float* b_out   = (const float*)d_in[6];
    float* out           = (float*)d_out;

    void* wH_ptr = nullptr;
    cudaGetSymbolAddress(&wH_ptr, g_wH);
    __half* wH = (__half*)wH_ptr;

    cudaFuncSetAttribute((const void*)fused_all_kernel,
                         cudaFuncAttributeMaxDynamicSharedMemorySize, FUSED_SMEM);

    // K0: weights -> fp16 transposed (tiny)
    prep_w_kernel<<<192, 256>>>(w_qkv, w_out, wH);

    // KF: fully fused LN + partition + QKV + attention + proj + merge
    fused_all_kernel<<<4096, 256, FUSED_SMEM>>>(x, wH, b_qkv, b_out, ln_g, ln_b, out);
}

// round 17
// speedup vs baseline: 1.8132x; 1.3890x over previous
#include <cuda_runtime.h>
#include <cuda_fp16.h>
#include <cstdint>

// ---------------------------------------------------------------------------
// Window-based self-attention (Swin-style), B=64, 56x56, C=128, WS=7, NH=8.
// Round 17: R16 fp16 pipeline + ldmatrix fragment loads (4x fewer LDS) +
// pre-fragmented weights (LDG.128). Values bit-identical to R16.
//   K0: weights -> fp16 mma fragments, uint4 per (block,s,lane)
//   KF: fused LN + partition + QKV GEMM + attention + out-proj + merge
// smem 57KB, 2 CTAs/SM.
// ---------------------------------------------------------------------------

#define SCALE_ATT 0.25f             // HD^-0.5, HD=16
#define LN_EPS    1e-5f

#define XS_LDAH   136               // xs/os row stride (halves)
#define QK_LDAH   24                // q/k slab row stride (halves)
#define VT_LDAH   72                // vt row stride (halves)
#define R1_OFF    9216              // halves: start of q/k slabs
#define SLAB_H    2352              // halves per head slab
#define FUSED_SMEM ((9216 + 8 * 2352 + 512) * 2)   // 57088 B

__device__ uint4 g_wF[32 * 8 * 32];   // [block(16-col)][s(k16)][lane] fragments

// ---------------------------------------------------------------------------
// helpers
// ---------------------------------------------------------------------------
__device__ __forceinline__ uint32_t pack_h2(float lo, float hi) {
    uint32_t d;
    asm("cvt.rn.f16x2.f32 %0, %1, %2;" : "=r"(d) : "f"(hi), "f"(lo));
    return d;
}
__device__ __forceinline__ void mma_f16(float* c,
                                        uint32_t a0, uint32_t a1, uint32_t a2, uint32_t a3,
                                        uint32_t b0, uint32_t b1) {
    asm volatile(
        "mma.sync.aligned.m16n8k16.row.col.f32.f16.f16.f32 "
        "{%0,%1,%2,%3}, {%4,%5,%6,%7}, {%8,%9}, {%0,%1,%2,%3};"
        : "+f"(c[0]), "+f"(c[1]), "+f"(c[2]), "+f"(c[3])
        : "r"(a0), "r"(a1), "r"(a2), "r"(a3), "r"(b0), "r"(b1));
}
__device__ __forceinline__ uint32_t smem_u32(const void* p) {
    uint32_t a;
    asm("{ .reg .u64 t; cvta.to.shared.u64 t, %1; cvt.u32.u64 %0, t; }" : "=r"(a) : "l"(p));
    return a;
}
__device__ __forceinline__ void ldmx4(uint32_t& r0, uint32_t& r1, uint32_t& r2,
                                      uint32_t& r3, uint32_t a) {
    asm volatile("ldmatrix.sync.aligned.m8n8.x4.shared.b16 {%0,%1,%2,%3}, [%4];"
                 : "=r"(r0), "=r"(r1), "=r"(r2), "=r"(r3) : "r"(a));
}
__device__ __forceinline__ void ldmx2(uint32_t& r0, uint32_t& r1, uint32_t a) {
    asm volatile("ldmatrix.sync.aligned.m8n8.x2.shared.b16 {%0,%1}, [%2];"
                 : "=r"(r0), "=r"(r1) : "r"(a));
}

// ---------------------------------------------------------------------------
// K0: weights -> fp16 fragment layout. Block = 16 output cols (0..23 qkv,
// 24..31 out-proj). For (block, s, lane): uint4 = (b[j=0][r=0..1], b[j=1][r=0..1]).
// ---------------------------------------------------------------------------
__global__ void prep_w_kernel(const float* __restrict__ wqkv,
                              const float* __restrict__ wout,
                              uint4* __restrict__ wF)
{
    const int idx = blockIdx.x * 256 + threadIdx.x;   // 8192 total
    if (idx >= 8192) return;
    const int lane = idx & 31, s = (idx >> 5) & 7, blk = idx >> 8;
    const int qrow = lane >> 2, qcol = lane & 3;
    const int k0 = 16 * s + 2 * qcol;
    uint4 t;
    if (blk < 24) {
        const int n0 = blk * 16 + qrow, n1 = n0 + 8;
        t.x = pack_h2(wqkv[k0 * 384 + n0],       wqkv[(k0 + 1) * 384 + n0]);
        t.y = pack_h2(wqkv[(k0 + 8) * 384 + n0], wqkv[(k0 + 9) * 384 + n0]);
        t.z = pack_h2(wqkv[k0 * 384 + n1],       wqkv[(k0 + 1) * 384 + n1]);
        t.w = pack_h2(wqkv[(k0 + 8) * 384 + n1], wqkv[(k0 + 9) * 384 + n1]);
    } else {
        const int n0 = (blk - 24) * 16 + qrow, n1 = n0 + 8;
        t.x = pack_h2(wout[k0 * 128 + n0],       wout[(k0 + 1) * 128 + n0]);
        t.y = pack_h2(wout[(k0 + 8) * 128 + n0], wout[(k0 + 9) * 128 + n0]);
        t.z = pack_h2(wout[k0 * 128 + n1],       wout[(k0 + 1) * 128 + n1]);
        t.w = pack_h2(wout[(k0 + 8) * 128 + n1], wout[(k0 + 9) * 128 + n1]);
    }
    wF[idx] = t;
}

// ---------------------------------------------------------------------------
// KF: fully fused per-window kernel. 1 CTA = 1 window, 256 threads (8 warps).
// ---------------------------------------------------------------------------
__global__ void __launch_bounds__(256, 2)
fused_all_kernel(const float* __restrict__ x,
                 const uint4* __restrict__ wF,     // weight fragments
                 const float* __restrict__ bqkv,   // [384]
                 const float* __restrict__ bout,   // [128]
                 const float* __restrict__ gamma,
                 const float* __restrict__ beta,
                 float* __restrict__ out)
{
    extern __shared__ __half smh[];
    __half* xs = smh;                              // [64][136]
    const int g    = blockIdx.x;                   // window
    const int tid  = threadIdx.x;
    const int warp = tid >> 5;                     // head / GEMM warp
    const int lane = tid & 31;
    const int qrow = lane >> 2;
    const int qcol = lane & 3;

    __half* qs_h = smh + R1_OFF + warp * SLAB_H;   // [49][24]
    __half* ks_h = qs_h + 49 * QK_LDAH;            // [49][24]
    __half* vt_h = smh + warp * (16 * VT_LDAH);    // [16][72], aliases xs
    __half* os   = smh + R1_OFF;                   // [64][136], aliases qs/ks

    const int b = g >> 6, w = g & 63;

    // ldmatrix base addresses (shared-space byte addrs)
    const int mi = lane >> 3, mr = lane & 7;       // x4: matrix idx / row
    const int l8 = lane & 7, lm = (lane >> 3) & 1; // x2: row / matrix idx
    const uint32_t aBaseLm = smem_u32(xs) +
        (uint32_t)((((mi & 1) * 8 + mr) * XS_LDAH + (mi >> 1) * 8) * 2);
    const uint32_t oBaseLm = smem_u32(os) +
        (uint32_t)((((mi & 1) * 8 + mr) * XS_LDAH + (mi >> 1) * 8) * 2);
    const uint32_t qBaseLm = smem_u32(qs_h) +
        (uint32_t)((((mi & 1) * 8 + mr) * QK_LDAH + (mi >> 1) * 8) * 2);
    const uint32_t kBaseLm = smem_u32(ks_h) + (uint32_t)((l8 * QK_LDAH + lm * 8) * 2);
    const uint32_t vBaseLm = smem_u32(vt_h) + (uint32_t)((l8 * VT_LDAH + lm * 8) * 2);

    // ---- Phase A: gather + LayerNorm -> xs rows 0..48 (fp16) ----
    {
        float4 gm = reinterpret_cast<const float4*>(gamma)[lane];
        float4 bt = reinterpret_cast<const float4*>(beta)[lane];
        const float4* X4 = reinterpret_cast<const float4*>(x);
        for (int p = warp; p < 49; p += 8) {
            const int row = (w >> 3) * 7 + p / 7;
            const int col = (w & 7) * 7 + p % 7;
            float4 v = X4[((size_t)b * 3136 + row * 56 + col) * 32 + lane];
            float sum = v.x + v.y + v.z + v.w;
            #pragma unroll
            for (int o = 16; o > 0; o >>= 1) sum += __shfl_xor_sync(0xffffffffu, sum, o);
            const float mu = sum * (1.0f / 128.0f);
            float4 d;
            d.x = v.x - mu; d.y = v.y - mu; d.z = v.z - mu; d.w = v.w - mu;
            float sq = d.x * d.x + d.y * d.y + d.z * d.z + d.w * d.w;
            #pragma unroll
            for (int o = 16; o > 0; o >>= 1) sq += __shfl_xor_sync(0xffffffffu, sq, o);
            const float rstd = rsqrtf(sq * (1.0f / 128.0f) + LN_EPS);
            uint2 hv;
            hv.x = pack_h2(d.x * rstd * gm.x + bt.x, d.y * rstd * gm.y + bt.y);
            hv.y = pack_h2(d.z * rstd * gm.z + bt.z, d.w * rstd * gm.w + bt.w);
            *reinterpret_cast<uint2*>(&xs[p * XS_LDAH + lane * 4]) = hv;
        }
    }
    __syncthreads();

    // ---- Phase B: QKV GEMM, 3 passes (q, k, v) ----
    #pragma unroll 1
    for (int pass = 0; pass < 3; pass++) {
        float acc[4][2][4];
        #pragma unroll
        for (int i = 0; i < 4; i++)
            #pragma unroll
            for (int j = 0; j < 2; j++)
                #pragma unroll
                for (int r = 0; r < 4; r++) acc[i][j][r] = 0.0f;

        // prefetch all B frags: 8 x LDG.128 (L2-hot)
        const uint4* wfp = wF + (size_t)(pass * 8 + warp) * 256 + lane;
        uint4 bb[8];
        #pragma unroll
        for (int s = 0; s < 8; s++) bb[s] = __ldg(&wfp[s * 32]);

        #pragma unroll
        for (int s = 0; s < 8; s++) {
            #pragma unroll
            for (int i = 0; i < 4; i++) {
                uint32_t a0, a1, a2, a3;
                ldmx4(a0, a1, a2, a3,
                      aBaseLm + (uint32_t)((i * 16 * XS_LDAH + s * 16) * 2));
                mma_f16(acc[i][0], a0, a1, a2, a3, bb[s].x, bb[s].y);
                mma_f16(acc[i][1], a0, a1, a2, a3, bb[s].z, bb[s].w);
            }
        }

        // before v epilogue (vt aliases xs) all warps must be done reading xs
        if (pass == 2) __syncthreads();

        #pragma unroll
        for (int i = 0; i < 4; i++) {
            #pragma unroll
            for (int half = 0; half < 2; half++) {
                const int r = i * 16 + qrow + half * 8;
                if (r < 49) {
                    #pragma unroll
                    for (int j = 0; j < 2; j++) {
                        const int d = j * 8 + 2 * qcol;
                        const int bidx = pass * 128 + warp * 16 + d;
                        const float vx = acc[i][j][half * 2 + 0] + __ldg(&bqkv[bidx]);
                        const float vy = acc[i][j][half * 2 + 1] + __ldg(&bqkv[bidx + 1]);
                        if (pass == 0) {
                            *reinterpret_cast<uint32_t*>(&qs_h[r * QK_LDAH + d]) =
                                pack_h2(vx * SCALE_ATT, vy * SCALE_ATT);
                        } else if (pass == 1) {
                            *reinterpret_cast<uint32_t*>(&ks_h[r * QK_LDAH + d]) =
                                pack_h2(vx, vy);
                        } else {
                            vt_h[d * VT_LDAH + r]       = __float2half_rn(vx);
                            vt_h[(d + 1) * VT_LDAH + r] = __float2half_rn(vy);
                        }
                    }
                }
            }
        }
    }

    // zero vt pad cols 49..63 (PV reads up to c=63)
    for (int i2 = lane; i2 < 240; i2 += 32) {
        const int d = i2 / 15, c = 49 + i2 % 15;
        vt_h[d * VT_LDAH + c] = __ushort_as_half((unsigned short)0);
    }
    __syncwarp();

    // ---- Phase C: attention (warp = head), O kept in registers ----
    float oall[2][2][2][4];                        // [rowhalf][i][jn][r]

    #pragma unroll 1
    for (int rowhalf = 0; rowhalf < 2; rowhalf++) {
        // scores: S = Q K^T — single k16 step
        float sc[2][7][4];
        #pragma unroll
        for (int i = 0; i < 2; i++)
            #pragma unroll
            for (int j = 0; j < 7; j++)
                #pragma unroll
                for (int r = 0; r < 4; r++) sc[i][j][r] = 0.0f;

        uint32_t ah[2][4];
        #pragma unroll
        for (int i = 0; i < 2; i++) {
            const int it = rowhalf * 2 + i;
            ldmx4(ah[i][0], ah[i][1], ah[i][2], ah[i][3],
                  qBaseLm + (uint32_t)(it * 16 * QK_LDAH * 2));
        }
        #pragma unroll
        for (int j = 0; j < 7; j++) {
            uint32_t b0, b1;
            ldmx2(b0, b1, kBaseLm + (uint32_t)(j * 8 * QK_LDAH * 2));
            #pragma unroll
            for (int i = 0; i < 2; i++)
                mma_f16(sc[i][j], ah[i][0], ah[i][1], ah[i][2], ah[i][3], b0, b1);
        }

        // softmax in C layout
        float invlo[2], invhi[2];
        #pragma unroll
        for (int i = 0; i < 2; i++) {
            if (qcol != 0) { sc[i][6][0] = -1e30f; sc[i][6][2] = -1e30f; }
            sc[i][6][1] = -1e30f; sc[i][6][3] = -1e30f;

            float mlo = -1e30f, mhi = -1e30f;
            #pragma unroll
            for (int j = 0; j < 7; j++) {
                mlo = fmaxf(mlo, fmaxf(sc[i][j][0], sc[i][j][1]));
                mhi = fmaxf(mhi, fmaxf(sc[i][j][2], sc[i][j][3]));
            }
            mlo = fmaxf(mlo, __shfl_xor_sync(0xffffffffu, mlo, 1));
            mlo = fmaxf(mlo, __shfl_xor_sync(0xffffffffu, mlo, 2));
            mhi = fmaxf(mhi, __shfl_xor_sync(0xffffffffu, mhi, 1));
            mhi = fmaxf(mhi, __shfl_xor_sync(0xffffffffu, mhi, 2));

            float slo = 0.0f, shi = 0.0f;
            #pragma unroll
            for (int j = 0; j < 7; j++) {
                sc[i][j][0] = __expf(sc[i][j][0] - mlo);
                sc[i][j][1] = __expf(sc[i][j][1] - mlo);
                sc[i][j][2] = __expf(sc[i][j][2] - mhi);
                sc[i][j][3] = __expf(sc[i][j][3] - mhi);
                slo += sc[i][j][0] + sc[i][j][1];
                shi += sc[i][j][2] + sc[i][j][3];
            }
            slo += __shfl_xor_sync(0xffffffffu, slo, 1);
            slo += __shfl_xor_sync(0xffffffffu, slo, 2);
            shi += __shfl_xor_sync(0xffffffffu, shi, 1);
            shi += __shfl_xor_sync(0xffffffffu, shi, 2);
            invlo[i] = 1.0f / slo;
            invhi[i] = 1.0f / shi;
        }

        // PV: O = P V. fp16 A-frags are the C-frag pairs — no shuffles.
        float oacc[2][2][4];
        #pragma unroll
        for (int i = 0; i < 2; i++)
            #pragma unroll
            for (int jn = 0; jn < 2; jn++)
                #pragma unroll
                for (int r = 0; r < 4; r++) oacc[i][jn][r] = 0.0f;

        #pragma unroll
        for (int kt = 0; kt < 4; kt++) {
            uint32_t Bh[2][2];
            #pragma unroll
            for (int jn = 0; jn < 2; jn++)
                ldmx2(Bh[jn][0], Bh[jn][1],
                      vBaseLm + (uint32_t)((jn * 8 * VT_LDAH + kt * 16) * 2));
            #pragma unroll
            for (int i = 0; i < 2; i++) {
                const uint32_t a0 = pack_h2(sc[i][2 * kt][0], sc[i][2 * kt][1]);
                const uint32_t a1 = pack_h2(sc[i][2 * kt][2], sc[i][2 * kt][3]);
                const uint32_t a2 = (kt < 3) ? pack_h2(sc[i][2 * kt + 1][0], sc[i][2 * kt + 1][1]) : 0u;
                const uint32_t a3 = (kt < 3) ? pack_h2(sc[i][2 * kt + 1][2], sc[i][2 * kt + 1][3]) : 0u;
                #pragma unroll
                for (int jn = 0; jn < 2; jn++)
                    mma_f16(oacc[i][jn], a0, a1, a2, a3, Bh[jn][0], Bh[jn][1]);
            }
        }

        #pragma unroll
        for (int i = 0; i < 2; i++)
            #pragma unroll
            for (int jn = 0; jn < 2; jn++) {
                oall[rowhalf][i][jn][0] = oacc[i][jn][0] * invlo[i];
                oall[rowhalf][i][jn][1] = oacc[i][jn][1] * invlo[i];
                oall[rowhalf][i][jn][2] = oacc[i][jn][2] * invhi[i];
                oall[rowhalf][i][jn][3] = oacc[i][jn][3] * invhi[i];
            }
    }

    // ---- Phase D: O -> os tile (aliases qs/ks), then out-proj GEMM ----
    __syncthreads();   // all warps done reading qs/ks before os overwrites

    #pragma unroll
    for (int rowhalf = 0; rowhalf < 2; rowhalf++)
        #pragma unroll
        for (int i = 0; i < 2; i++) {
            const int it = rowhalf * 2 + i;
            const int rlo = it * 16 + qrow;
            const int rhi = rlo + 8;
            #pragma unroll
            for (int jn = 0; jn < 2; jn++) {
                const int d = warp * 16 + jn * 8 + 2 * qcol;
                if (rlo < 49)
                    *reinterpret_cast<uint32_t*>(&os[rlo * XS_LDAH + d]) =
                        pack_h2(oall[rowhalf][i][jn][0], oall[rowhalf][i][jn][1]);
                if (rhi < 49)
                    *reinterpret_cast<uint32_t*>(&os[rhi * XS_LDAH + d]) =
                        pack_h2(oall[rowhalf][i][jn][2], oall[rowhalf][i][jn][3]);
            }
        }
    // zero pad rows 49..63
    for (int i2 = tid; i2 < 15 * XS_LDAH; i2 += 256)
        os[49 * XS_LDAH + i2] = __ushort_as_half((unsigned short)0);
    __syncthreads();

    // proj GEMM: A = os, B = out-proj fragments (blocks 24..31)
    {
        float acc[4][2][4];
        #pragma unroll
        for (int i = 0; i < 4; i++)
            #pragma unroll
            for (int j = 0; j < 2; j++)
                #pragma unroll
                for (int r = 0; r < 4; r++) acc[i][j][r] = 0.0f;

        const uint4* wfp = wF + (size_t)(24 + warp) * 256 + lane;
        uint4 bb[8];
        #pragma unroll
        for (int s = 0; s < 8; s++) bb[s] = __ldg(&wfp[s * 32]);

        #pragma unroll
        for (int s = 0; s < 8; s++) {
            #pragma unroll
            for (int i = 0; i < 4; i++) {
                uint32_t a0, a1, a2, a3;
                ldmx4(a0, a1, a2, a3,
                      oBaseLm + (uint32_t)((i * 16 * XS_LDAH + s * 16) * 2));
                mma_f16(acc[i][0], a0, a1, a2, a3, bb[s].x, bb[s].y);
                mma_f16(acc[i][1], a0, a1, a2, a3, bb[s].z, bb[s].w);
            }
        }

        // epilogue: +bias, window-merge scatter to d_out (f32)
        #pragma unroll
        for (int i = 0; i < 4; i++) {
            #pragma unroll
            for (int half = 0; half < 2; half++) {
                const int p = i * 16 + qrow + half * 8;
                if (p < 49) {
                    const int row = (w >> 3) * 7 + p / 7;
                    const int col = (w & 7) * 7 + p % 7;
                    float* op = out + ((size_t)b * 3136 + row * 56 + col) * 128;
                    #pragma unroll
                    for (int j = 0; j < 2; j++) {
                        const int cofs = warp * 16 + j * 8 + 2 * qcol;
                        float2 v;
                        v.x = acc[i][j][half * 2 + 0] + __ldg(&bout[cofs]);
                        v.y = acc[i][j][half * 2 + 1] + __ldg(&bout[cofs + 1]);
                        *reinterpret_cast<float2*>(op + cofs) = v;
                    }
                }
            }
        }
    }
}

// ---------------------------------------------------------------------------
// Launch
// ---------------------------------------------------------------------------
extern "C" void kernel_launch(void* const* d_in, const int* in_sizes, int n_in,
                              void* d_out, int out_size)
{
    const float* x       = (const float*)d_in[0];
    const float* ln_g    = (const float*)d_in[1];
    const float* ln_b    = (const float*)d_in[2];
    const float* w_qkv   = (const float*)d_in[3];
    const float* b_qkv   = (const float*)d_in[4];
    const float* w_out   = (const float*)d_in[5];
    const float* b_out   = (const float*)d_in[6];
    float* out           = (float*)d_out;

    void* wF_ptr = nullptr;
    cudaGetSymbolAddress(&wF_ptr, g_wF);
    uint4* wF = (uint4*)wF_ptr;

    cudaFuncSetAttribute((const void*)fused_all_kernel,
                         cudaFuncAttributeMaxDynamicSharedMemorySize, FUSED_SMEM);

    // K0: weights -> fp16 fragment layout (tiny)
    prep_w_kernel<<<32, 256>>>(w_qkv, w_out, wF);

    // KF: fully fused LN + partition + QKV + attention + proj + merge
    fused_all_kernel<<<4096, 256, FUSED_SMEM>>>(x, wF, b_qkv, b_out, ln_g, ln_b, out);
}